// round 14
// baseline (speedup 1.0000x reference)
#include <cuda_runtime.h>
#include <cstdint>

// Fixed problem: n=4, c=16, h=w=64, patch=3
#define NB 4
#define CH 16
#define W 64
#define HW 4096
#define NDIAG 127
#define RST 67            // Rbuf row stride (67 % 32 = 3 -> conflict-free cols)
#define ABST 68           // A/B buffer row stride
#define NSTG 1122         // 17 rows x 66 staged values per operand

#define CY(v) (min(max((v), 0), 63))

__device__ float g_sm2[NB * CH * HW];   // -2 * s
__device__ float g_eS[NB * HW];
__device__ float g_eT[NB * HW];
__device__ unsigned long long g_best[NB * HW];

// ---------------------------------------------------------------------------
// Per-pixel channel sum of squares (eS / eT); y==0 also writes -2*s and
// resets g_best.
// ---------------------------------------------------------------------------
__global__ void norm1_kernel(const float* __restrict__ s, const float* __restrict__ t) {
    int idx = blockIdx.x * blockDim.x + threadIdx.x;
    if (idx >= NB * HW) return;
    const float* src = blockIdx.y ? t : s;
    int b = idx >> 12, pix = idx & (HW - 1);
    float acc = 0.f;
#pragma unroll
    for (int c = 0; c < CH; c++) {
        float v = src[((size_t)(b * CH + c) << 12) + pix];
        if (!blockIdx.y) g_sm2[((size_t)(b * CH + c) << 12) + pix] = -2.f * v;
        acc = fmaf(v, v, acc);
    }
    if (blockIdx.y) {
        g_eT[idx] = acc;
    } else {
        g_eS[idx] = acc;
        g_best[idx] = ~0ull;
    }
}

// ---------------------------------------------------------------------------
// Diagonal sweep kernel (R11 structure, occupancy 3).
// Block = (batch b, diagonal d = jy - iy), 508 blocks.
// R~(p, p+d)(ix~, jx~) is a K=18 GEMM folding both norms:
//   ch 0..15: (-2 s)[c][CY(p-1)][CY(ix~-1)] * t[c][CY(p+d-1)][CY(jx~-1)]
//   ch 16   : eS~(p, ix~) * 1
//   ch 17   : 1 * eT~(p+d, jx~)
// d2(iy, jy=iy+d)(ix,jx) = sum_uy Gx(p=iy+uy), Gx = diag-x-stencil of R~.
// Double-buffered register staging; warmup steps peeled; argmin merged to
// global atomicMin on packed key (d2bits<<12 | j) = exact first occurrence.
// ---------------------------------------------------------------------------
__global__ __launch_bounds__(256, 3) void nn_kernel(const float* __restrict__ t) {
    __shared__ float Abuf[2][18 * ABST];
    __shared__ float Bbuf[2][18 * ABST];
    __shared__ float Rbuf[66 * RST];

    const int tid = threadIdx.x;
    const int blk = blockIdx.x;
    const int kk = blk >> 2;            // diagonal index 0..126 (|d| ascending)
    const int b = blk & 3;
    const int d = (kk == 0) ? 0 : ((kk & 1) ? ((kk + 1) >> 1) : -(kk >> 1));
    const int lo = max(0, -d);
    const int steps = 66 - abs(d);

    const float* tB = t + ((size_t)b * CH << 12);
    const float* s2B = g_sm2 + ((size_t)b * CH << 12);
    const float* eSb = g_eS + b * HW;
    const float* eTb = g_eT + b * HW;

    // ---- staging precompute: 5 (A,B) elements per thread ----
    const float* pA[5]; const float* pB[5];
    unsigned dA[5], dB[5]; bool val[5];
    float rA[5], rB[5];
#pragma unroll
    for (int q = 0; q < 5; q++) {
        int u = tid + 256 * q;
        val[q] = (u < NSTG);
        int uu = val[q] ? u : 0;
        int m = uu / 66, xx = uu - 66 * m;
        int gx = CY(xx - 1);
        pA[q] = (m < 16) ? (s2B + (m << 12) + gx) : (eSb + gx);
        dA[q] = m * ABST + xx;
        pB[q] = (m < 16) ? (tB + (m << 12) + gx) : (eTb + gx);
        dB[q] = ((m == 16) ? 17 : m) * ABST + xx;
    }
    // constant channels in both buffers: A ch17 = 1, B ch16 = 1
    if (tid < 66) {
        Abuf[0][17 * ABST + tid] = 1.f;
        Abuf[1][17 * ABST + tid] = 1.f;
        Bbuf[0][16 * ABST + tid] = 1.f;
        Bbuf[1][16 * ABST + tid] = 1.f;
    }

    // prologue: stage p = lo into buf0, prefetch p = lo+1 into regs
    {
        int ra = CY(lo - 1) * W, rb = CY(lo + d - 1) * W;
#pragma unroll
        for (int q = 0; q < 5; q++) if (val[q]) {
            Abuf[0][dA[q]] = __ldg(pA[q] + ra);
            Bbuf[0][dB[q]] = __ldg(pB[q] + rb);
        }
        if (steps > 1) {
            int ra1 = CY(lo) * W, rb1 = CY(lo + d) * W;
#pragma unroll
            for (int q = 0; q < 5; q++) if (val[q]) {
                rA[q] = __ldg(pA[q] + ra1);
                rB[q] = __ldg(pB[q] + rb1);
            }
        }
    }

    // GEMM fragment mapping: 242 active threads, 3 ix~ x 6 jx~ each
    const bool act = tid < 242;
    const int ti = act ? (tid / 11) : 0;
    const int tj = act ? (tid - 11 * ti) : 0;

    // epilogue mapping: query ix = eix, jx band = 16*eg
    const int eix = tid & 63;
    const int eg = tid >> 6;
    const int ejx0 = eg << 4;
    const float* R0 = Rbuf + eix * RST + ejx0;
    const float* R1 = Rbuf + (eix + 1) * RST + ejx0 + 1;
    const float* R2 = Rbuf + (eix + 2) * RST + ejx0 + 2;
    unsigned long long* gb = g_best + b * HW + eix;

    float A1[16], A2[16];
#pragma unroll
    for (int jj = 0; jj < 16; jj++) { A1[jj] = 0.f; A2[jj] = 0.f; }

    // one step: GEMM buf[cur] -> Rbuf; stage next; prefetch next-next
#define GEMM_AND_STAGE(ss_)                                                    \
    do {                                                                       \
        const int cur = (ss_) & 1;                                             \
        __syncthreads();                                                       \
        if (act) {                                                             \
            float acc[3][6];                                                   \
            _Pragma("unroll")                                                  \
            for (int m = 0; m < 3; m++)                                        \
                _Pragma("unroll")                                              \
                for (int n = 0; n < 6; n++) acc[m][n] = 0.f;                   \
            const float* Ap = Abuf[cur] + 3 * ti;                              \
            const float* Bp = Bbuf[cur] + 6 * tj;                              \
            _Pragma("unroll 6")                                                \
            for (int k = 0; k < 18; k++) {                                     \
                float a0 = Ap[k * ABST], a1 = Ap[k * ABST + 1],                \
                      a2 = Ap[k * ABST + 2];                                   \
                float2 b0 = *(const float2*)(Bp + k * ABST);                   \
                float2 b1 = *(const float2*)(Bp + k * ABST + 2);               \
                float2 b2 = *(const float2*)(Bp + k * ABST + 4);               \
                acc[0][0] = fmaf(a0, b0.x, acc[0][0]);                         \
                acc[0][1] = fmaf(a0, b0.y, acc[0][1]);                         \
                acc[0][2] = fmaf(a0, b1.x, acc[0][2]);                         \
                acc[0][3] = fmaf(a0, b1.y, acc[0][3]);                         \
                acc[0][4] = fmaf(a0, b2.x, acc[0][4]);                         \
                acc[0][5] = fmaf(a0, b2.y, acc[0][5]);                         \
                acc[1][0] = fmaf(a1, b0.x, acc[1][0]);                         \
                acc[1][1] = fmaf(a1, b0.y, acc[1][1]);                         \
                acc[1][2] = fmaf(a1, b1.x, acc[1][2]);                         \
                acc[1][3] = fmaf(a1, b1.y, acc[1][3]);                         \
                acc[1][4] = fmaf(a1, b2.x, acc[1][4]);                         \
                acc[1][5] = fmaf(a1, b2.y, acc[1][5]);                         \
                acc[2][0] = fmaf(a2, b0.x, acc[2][0]);                         \
                acc[2][1] = fmaf(a2, b0.y, acc[2][1]);                         \
                acc[2][2] = fmaf(a2, b1.x, acc[2][2]);                         \
                acc[2][3] = fmaf(a2, b1.y, acc[2][3]);                         \
                acc[2][4] = fmaf(a2, b2.x, acc[2][4]);                         \
                acc[2][5] = fmaf(a2, b2.y, acc[2][5]);                         \
            }                                                                  \
            _Pragma("unroll")                                                  \
            for (int m = 0; m < 3; m++)                                        \
                _Pragma("unroll")                                              \
                for (int n = 0; n < 6; n++)                                    \
                    Rbuf[(3 * ti + m) * RST + 6 * tj + n] = acc[m][n];         \
        }                                                                      \
        if ((ss_) + 1 < steps) {                                               \
            _Pragma("unroll")                                                  \
            for (int q = 0; q < 5; q++) if (val[q]) {                          \
                Abuf[cur ^ 1][dA[q]] = rA[q];                                  \
                Bbuf[cur ^ 1][dB[q]] = rB[q];                                  \
            }                                                                  \
        }                                                                      \
        if ((ss_) + 2 < steps) {                                               \
            int pn = lo + (ss_) + 2;                                           \
            int ra = CY(pn - 1) * W, rb = CY(pn + d - 1) * W;                  \
            _Pragma("unroll")                                                  \
            for (int q = 0; q < 5; q++) if (val[q]) {                          \
                rA[q] = __ldg(pA[q] + ra);                                     \
                rB[q] = __ldg(pB[q] + rb);                                     \
            }                                                                  \
        }                                                                      \
        __syncthreads();                                                       \
    } while (0)

    // ---- warmup: ss = 0, 1 (window fill only, no argmin) ----
#pragma unroll 1
    for (int ss = 0; ss < 2 && ss < steps; ss++) {
        GEMM_AND_STAGE(ss);
#pragma unroll
        for (int jj = 0; jj < 16; jj++) {
            float g = R0[jj] + R1[jj] + R2[jj];
            A2[jj] = A1[jj] + g;
            A1[jj] = g;
        }
    }

    // ---- main: ss = 2..steps-1, one finished row per step ----
#pragma unroll 1
    for (int ss = 2; ss < steps; ss++) {
        GEMM_AND_STAGE(ss);
        const int iy = lo + ss - 2;
        unsigned long long cand = ~0ull;
        const unsigned jrow = (unsigned)((iy + d) * W + ejx0);
#pragma unroll
        for (int jj = 0; jj < 16; jj++) {
            float g = R0[jj] + R1[jj] + R2[jj];
            float d2 = A2[jj] + g;
            unsigned long long key =
                ((unsigned long long)__float_as_uint(d2) << 12) | (jrow + jj);
            cand = key < cand ? key : cand;
            A2[jj] = A1[jj] + g;
            A1[jj] = g;
        }
        atomicMin(gb + iy * W, cand);
    }
#undef GEMM_AND_STAGE
}

// ---------------------------------------------------------------------------
// Decode packed keys -> (jy, jx, d2).
// ---------------------------------------------------------------------------
__global__ void reduce_kernel(float* __restrict__ out) {
    int idx = blockIdx.x * blockDim.x + threadIdx.x;
    if (idx >= NB * HW) return;
    int b = idx >> 12, q = idx & (HW - 1);
    unsigned long long best = g_best[idx];
    int j = (int)(best & 4095u);
    float d2 = __uint_as_float((unsigned)(best >> 12));
    out[(size_t)b * 2 * HW + q]                    = (float)(j >> 6);
    out[(size_t)b * 2 * HW + HW + q]               = (float)(j & 63);
    out[(size_t)NB * 2 * HW + (size_t)b * HW + q]  = d2;
}

extern "C" void kernel_launch(void* const* d_in, const int* in_sizes, int n_in,
                              void* d_out, int out_size) {
    const float* s = (const float*)d_in[0];
    const float* t = (const float*)d_in[1];
    float* out = (float*)d_out;

    norm1_kernel<<<dim3((NB * HW + 255) / 256, 2), 256>>>(s, t);
    nn_kernel<<<NDIAG * NB, 256>>>(t);
    reduce_kernel<<<(NB * HW + 255) / 256, 256>>>(out);
}

// round 15
// speedup vs baseline: 1.2342x; 1.2342x over previous
#include <cuda_runtime.h>
#include <cstdint>

// Fixed problem: n=4, c=16, h=w=64, patch=3
#define NB 4
#define CH 16
#define W 64
#define HW 4096
#define NDIAG 127
#define RST 67            // Rbuf row stride (67 % 32 = 3 -> conflict-free cols)
#define ABSTA 134         // duplicated A row stride (float2 pairs, 8B aligned)
#define ABSTB 68          // B row stride
#define NSTG 1122         // 17 rows x 66 staged values per operand

#define CY(v) (min(max((v), 0), 63))

__device__ float g_sm2[NB * CH * HW];   // -2 * s
__device__ float g_eS[NB * HW];
__device__ float g_eT[NB * HW];
__device__ unsigned long long g_best[NB * HW];

__device__ __forceinline__ unsigned long long ffma2(unsigned long long a,
                                                    unsigned long long b,
                                                    unsigned long long c) {
    asm("fma.rn.f32x2 %0, %1, %2, %0;" : "+l"(c) : "l"(a), "l"(b));
    return c;
}

// ---------------------------------------------------------------------------
// Per-pixel channel sum of squares (eS / eT); y==0 also writes -2*s and
// resets g_best.
// ---------------------------------------------------------------------------
__global__ void norm1_kernel(const float* __restrict__ s, const float* __restrict__ t) {
    int idx = blockIdx.x * blockDim.x + threadIdx.x;
    if (idx >= NB * HW) return;
    const float* src = blockIdx.y ? t : s;
    int b = idx >> 12, pix = idx & (HW - 1);
    float acc = 0.f;
#pragma unroll
    for (int c = 0; c < CH; c++) {
        float v = src[((size_t)(b * CH + c) << 12) + pix];
        if (!blockIdx.y) g_sm2[((size_t)(b * CH + c) << 12) + pix] = -2.f * v;
        acc = fmaf(v, v, acc);
    }
    if (blockIdx.y) {
        g_eT[idx] = acc;
    } else {
        g_eS[idx] = acc;
        g_best[idx] = ~0ull;
    }
}

// ---------------------------------------------------------------------------
// Diagonal sweep kernel (R11 structure, packed f32x2 GEMM).
// Block = (batch b, diagonal d = jy - iy), 508 blocks.
// R~(p, p+d)(ix~, jx~) is a K=18 GEMM folding both norms:
//   ch 0..15: (-2 s)[c][CY(p-1)][CY(ix~-1)] * t[c][CY(p+d-1)][CY(jx~-1)]
//   ch 16   : eS~(p, ix~) * 1
//   ch 17   : 1 * eT~(p+d, jx~)
// A staged duplicated ((v,v) pairs) so LDS.64 feeds FFMA2 directly; B pairs
// along jx. d2 = sliding-window sum of diag-x-stencils; argmin via global
// atomicMin on packed key (d2bits<<12 | j) = exact first occurrence.
// ---------------------------------------------------------------------------
__global__ __launch_bounds__(256, 2) void nn_kernel(const float* __restrict__ t) {
    __shared__ float Abuf[2][18 * ABSTA];   // duplicated pairs
    __shared__ float Bbuf[2][18 * ABSTB];
    __shared__ float Rbuf[66 * RST];

    const int tid = threadIdx.x;
    const int blk = blockIdx.x;
    const int kk = blk >> 2;            // diagonal index 0..126 (|d| ascending)
    const int b = blk & 3;
    const int d = (kk == 0) ? 0 : ((kk & 1) ? ((kk + 1) >> 1) : -(kk >> 1));
    const int lo = max(0, -d);
    const int steps = 66 - abs(d);

    const float* tB = t + ((size_t)b * CH << 12);
    const float* s2B = g_sm2 + ((size_t)b * CH << 12);
    const float* eSb = g_eS + b * HW;
    const float* eTb = g_eT + b * HW;

    // ---- staging precompute: 5 (A,B) elements per thread ----
    const float* pA[5]; const float* pB[5];
    unsigned dA[5], dB[5]; bool val[5];
    float rA[5], rB[5];
#pragma unroll
    for (int q = 0; q < 5; q++) {
        int u = tid + 256 * q;
        val[q] = (u < NSTG);
        int uu = val[q] ? u : 0;
        int m = uu / 66, xx = uu - 66 * m;
        int gx = CY(xx - 1);
        pA[q] = (m < 16) ? (s2B + (m << 12) + gx) : (eSb + gx);
        dA[q] = m * ABSTA + 2 * xx;          // duplicated position
        pB[q] = (m < 16) ? (tB + (m << 12) + gx) : (eTb + gx);
        dB[q] = ((m == 16) ? 17 : m) * ABSTB + xx;
    }
    // constant channels in both buffers: A ch17 = 1 (dup), B ch16 = 1
    if (tid < 66) {
        float2 one2 = make_float2(1.f, 1.f);
        *(float2*)&Abuf[0][17 * ABSTA + 2 * tid] = one2;
        *(float2*)&Abuf[1][17 * ABSTA + 2 * tid] = one2;
        Bbuf[0][16 * ABSTB + tid] = 1.f;
        Bbuf[1][16 * ABSTB + tid] = 1.f;
    }

    // prologue: stage p = lo into buf0, prefetch p = lo+1 into regs
    {
        int ra = CY(lo - 1) * W, rb = CY(lo + d - 1) * W;
#pragma unroll
        for (int q = 0; q < 5; q++) if (val[q]) {
            float av = __ldg(pA[q] + ra);
            *(float2*)&Abuf[0][dA[q]] = make_float2(av, av);
            Bbuf[0][dB[q]] = __ldg(pB[q] + rb);
        }
        if (steps > 1) {
            int ra1 = CY(lo) * W, rb1 = CY(lo + d) * W;
#pragma unroll
            for (int q = 0; q < 5; q++) if (val[q]) {
                rA[q] = __ldg(pA[q] + ra1);
                rB[q] = __ldg(pB[q] + rb1);
            }
        }
    }

    // GEMM fragment mapping: 242 active threads, 3 ix~ x 6 jx~ each
    const bool act = tid < 242;
    const int ti = act ? (tid / 11) : 0;
    const int tj = act ? (tid - 11 * ti) : 0;

    // epilogue mapping: query ix = eix, jx band = 16*eg
    const int eix = tid & 63;
    const int eg = tid >> 6;
    const int ejx0 = eg << 4;
    const float* R0 = Rbuf + eix * RST + ejx0;
    const float* R1 = Rbuf + (eix + 1) * RST + ejx0 + 1;
    const float* R2 = Rbuf + (eix + 2) * RST + ejx0 + 2;
    unsigned long long* gb = g_best + b * HW + eix;

    float A1[16], A2[16];
#pragma unroll
    for (int jj = 0; jj < 16; jj++) { A1[jj] = 0.f; A2[jj] = 0.f; }

    for (int ss = 0; ss < steps; ss++) {
        const int cur = ss & 1;
        __syncthreads();   // buf[cur] staged; prev epilogue done with Rbuf

        // ---- K=18 packed-f32x2 GEMM from buf[cur] -> R~ tile ----
        if (act) {
            unsigned long long acc[3][3];
#pragma unroll
            for (int m = 0; m < 3; m++)
#pragma unroll
                for (int n = 0; n < 3; n++) acc[m][n] = 0ull;
            const float* Ap = Abuf[cur] + 6 * ti;   // duplicated pairs
            const float* Bp = Bbuf[cur] + 6 * tj;
#pragma unroll 6
            for (int k = 0; k < 18; k++) {
                unsigned long long a0 = *(const unsigned long long*)(Ap + k * ABSTA);
                unsigned long long a1 = *(const unsigned long long*)(Ap + k * ABSTA + 2);
                unsigned long long a2 = *(const unsigned long long*)(Ap + k * ABSTA + 4);
                unsigned long long b0 = *(const unsigned long long*)(Bp + k * ABSTB);
                unsigned long long b1 = *(const unsigned long long*)(Bp + k * ABSTB + 2);
                unsigned long long b2 = *(const unsigned long long*)(Bp + k * ABSTB + 4);
                acc[0][0] = ffma2(a0, b0, acc[0][0]);
                acc[0][1] = ffma2(a0, b1, acc[0][1]);
                acc[0][2] = ffma2(a0, b2, acc[0][2]);
                acc[1][0] = ffma2(a1, b0, acc[1][0]);
                acc[1][1] = ffma2(a1, b1, acc[1][1]);
                acc[1][2] = ffma2(a1, b2, acc[1][2]);
                acc[2][0] = ffma2(a2, b0, acc[2][0]);
                acc[2][1] = ffma2(a2, b1, acc[2][1]);
                acc[2][2] = ffma2(a2, b2, acc[2][2]);
            }
#pragma unroll
            for (int m = 0; m < 3; m++)
#pragma unroll
                for (int n = 0; n < 3; n++) {
                    float* dst = Rbuf + (3 * ti + m) * RST + 6 * tj + 2 * n;
                    dst[0] = __uint_as_float((unsigned)(acc[m][n] & 0xffffffffull));
                    dst[1] = __uint_as_float((unsigned)(acc[m][n] >> 32));
                }
        }

        // ---- stage next row pair into buf[cur^1]; prefetch the one after ----
        if (ss + 1 < steps) {
#pragma unroll
            for (int q = 0; q < 5; q++) if (val[q]) {
                *(float2*)&Abuf[cur ^ 1][dA[q]] = make_float2(rA[q], rA[q]);
                Bbuf[cur ^ 1][dB[q]] = rB[q];
            }
        }
        if (ss + 2 < steps) {
            int pn = lo + ss + 2;
            int ra = CY(pn - 1) * W, rb = CY(pn + d - 1) * W;
#pragma unroll
            for (int q = 0; q < 5; q++) if (val[q]) {
                rA[q] = __ldg(pA[q] + ra);
                rB[q] = __ldg(pB[q] + rb);
            }
        }
        __syncthreads();   // Rbuf writes visible

        // ---- epilogue: diag-x-stencil, sliding window, argmin on finish ----
        const bool fin = (ss >= 2);
        const int jy = lo + ss - 2 + d;
        unsigned long long cand = ~0ull;
        const unsigned jrow = (unsigned)(jy * W + ejx0);
#pragma unroll
        for (int jj = 0; jj < 16; jj++) {
            float g = R0[jj] + R1[jj] + R2[jj];
            if (fin) {
                float d2 = A2[jj] + g;
                unsigned long long key =
                    ((unsigned long long)__float_as_uint(d2) << 12) | (jrow + jj);
                cand = key < cand ? key : cand;
            }
            A2[jj] = A1[jj] + g;
            A1[jj] = g;
        }
        if (fin) {
            int iy = lo + ss - 2;
            atomicMin(gb + iy * W, cand);
        }
    }
}

// ---------------------------------------------------------------------------
// Decode packed keys -> (jy, jx, d2).
// ---------------------------------------------------------------------------
__global__ void reduce_kernel(float* __restrict__ out) {
    int idx = blockIdx.x * blockDim.x + threadIdx.x;
    if (idx >= NB * HW) return;
    int b = idx >> 12, q = idx & (HW - 1);
    unsigned long long best = g_best[idx];
    int j = (int)(best & 4095u);
    float d2 = __uint_as_float((unsigned)(best >> 12));
    out[(size_t)b * 2 * HW + q]                    = (float)(j >> 6);
    out[(size_t)b * 2 * HW + HW + q]               = (float)(j & 63);
    out[(size_t)NB * 2 * HW + (size_t)b * HW + q]  = d2;
}

extern "C" void kernel_launch(void* const* d_in, const int* in_sizes, int n_in,
                              void* d_out, int out_size) {
    const float* s = (const float*)d_in[0];
    const float* t = (const float*)d_in[1];
    float* out = (float*)d_out;

    norm1_kernel<<<dim3((NB * HW + 255) / 256, 2), 256>>>(s, t);
    nn_kernel<<<NDIAG * NB, 256>>>(t);
    reduce_kernel<<<(NB * HW + 255) / 256, 256>>>(out);
}

// round 16
// speedup vs baseline: 1.4983x; 1.2140x over previous
#include <cuda_runtime.h>
#include <cstdint>

// Fixed problem: n=4, c=16, h=w=64, patch=3
#define NB 4
#define CH 16
#define W 64
#define HW 4096
#define NDIAG 127
#define RST 67            // Rbuf row stride (67 % 32 = 3 -> conflict-free cols)
#define ABST 68           // A/B buffer row stride
#define NSTG 1122         // 17 rows x 66 staged values per operand

#define CY(v) (min(max((v), 0), 63))

__device__ float g_sm2[NB * CH * HW];   // -2 * s
__device__ float g_eS[NB * HW];
__device__ float g_eT[NB * HW];
__device__ unsigned long long g_best[NB * HW];

// ---------------------------------------------------------------------------
// Per-pixel channel sum of squares (eS / eT); y==0 also writes -2*s and
// resets g_best.
// ---------------------------------------------------------------------------
__global__ void norm1_kernel(const float* __restrict__ s, const float* __restrict__ t) {
    int idx = blockIdx.x * blockDim.x + threadIdx.x;
    if (idx >= NB * HW) return;
    const float* src = blockIdx.y ? t : s;
    int b = idx >> 12, pix = idx & (HW - 1);
    float acc = 0.f;
#pragma unroll
    for (int c = 0; c < CH; c++) {
        float v = src[((size_t)(b * CH + c) << 12) + pix];
        if (!blockIdx.y) g_sm2[((size_t)(b * CH + c) << 12) + pix] = -2.f * v;
        acc = fmaf(v, v, acc);
    }
    if (blockIdx.y) {
        g_eT[idx] = acc;
    } else {
        g_eS[idx] = acc;
        g_best[idx] = ~0ull;
    }
}

// ---------------------------------------------------------------------------
// Diagonal sweep kernel (R11 skeleton; 6x6 GEMM fragments on warps 0-3,
// staging on warps 4-7, float-domain argmin compare).
// Block = (batch b, diagonal d = jy - iy), 508 blocks.
// R~(p, p+d)(ix~, jx~) is a K=18 GEMM folding both norms:
//   ch 0..15: (-2 s)[c][CY(p-1)][CY(ix~-1)] * t[c][CY(p+d-1)][CY(jx~-1)]
//   ch 16   : eS~(p, ix~) * 1
//   ch 17   : 1 * eT~(p+d, jx~)
// d2(iy, jy=iy+d)(ix,jx) = sum_uy Gx(p=iy+uy), Gx = diag-x-stencil of R~.
// Argmin merged to global atomicMin on packed key (d2bits<<12 | j).
// ---------------------------------------------------------------------------
__global__ __launch_bounds__(256, 2) void nn_kernel(const float* __restrict__ t) {
    __shared__ float Abuf[2][18 * ABST];
    __shared__ float Bbuf[2][18 * ABST];
    __shared__ float Rbuf[66 * RST];

    const int tid = threadIdx.x;
    const int blk = blockIdx.x;
    const int kk = blk >> 2;            // diagonal index 0..126 (|d| ascending)
    const int b = blk & 3;
    const int d = (kk == 0) ? 0 : ((kk & 1) ? ((kk + 1) >> 1) : -(kk >> 1));
    const int lo = max(0, -d);
    const int steps = 66 - abs(d);

    const float* tB = t + ((size_t)b * CH << 12);
    const float* s2B = g_sm2 + ((size_t)b * CH << 12);
    const float* eSb = g_eS + b * HW;
    const float* eTb = g_eT + b * HW;

    // ---- staging state (warps 4-7 only): 9 (A,B) elements per thread ----
    const bool stager = tid >= 128;
    int srcOff[9]; int dstA[9]; bool m16[9]; bool ok[9];
    float rA[9], rB[9];
    if (stager) {
        int st = tid - 128;
#pragma unroll
        for (int q = 0; q < 9; q++) {
            int u = st + 128 * q;
            ok[q] = (u < NSTG);
            int uu = ok[q] ? u : 0;
            int m = uu / 66, xx = uu - 66 * m;
            int gx = CY(xx - 1);
            m16[q] = (m == 16);
            srcOff[q] = (m16[q] ? 0 : (m << 12)) + gx;
            dstA[q] = m * ABST + xx;
        }
    }
    // constant channels in both buffers: A ch17 = 1, B ch16 = 1
    if (tid < 66) {
        Abuf[0][17 * ABST + tid] = 1.f;
        Abuf[1][17 * ABST + tid] = 1.f;
        Bbuf[0][16 * ABST + tid] = 1.f;
        Bbuf[1][16 * ABST + tid] = 1.f;
    }

    // prologue: stage p = lo into buf0; prefetch p = lo+1 into regs
    if (stager) {
        int raw = CY(lo - 1) * W, rbw = CY(lo + d - 1) * W;
#pragma unroll
        for (int q = 0; q < 9; q++) if (ok[q]) {
            const float* bA = m16[q] ? eSb : s2B;
            const float* bB = m16[q] ? eTb : tB;
            Abuf[0][dstA[q]] = __ldg(bA + srcOff[q] + raw);
            Bbuf[0][dstA[q] + (m16[q] ? ABST : 0)] = __ldg(bB + srcOff[q] + rbw);
        }
        if (steps > 1) {
            int ra1 = CY(lo) * W, rb1 = CY(lo + d) * W;
#pragma unroll
            for (int q = 0; q < 9; q++) if (ok[q]) {
                const float* bA = m16[q] ? eSb : s2B;
                const float* bB = m16[q] ? eTb : tB;
                rA[q] = __ldg(bA + srcOff[q] + ra1);
                rB[q] = __ldg(bB + srcOff[q] + rb1);
            }
        }
    }

    // GEMM fragment mapping: 121 threads (warps 0-3), 6 ix~ x 6 jx~ each
    const bool act = tid < 121;
    const int ti = act ? (tid / 11) : 0;
    const int tj = act ? (tid - 11 * ti) : 0;

    // epilogue mapping: query ix = eix, jx band = 16*eg
    const int eix = tid & 63;
    const int eg = tid >> 6;
    const int ejx0 = eg << 4;
    const float* R0 = Rbuf + eix * RST + ejx0;
    const float* R1 = Rbuf + (eix + 1) * RST + ejx0 + 1;
    const float* R2 = Rbuf + (eix + 2) * RST + ejx0 + 2;
    unsigned long long* gb = g_best + b * HW + eix;

    float A1[16], A2[16];
#pragma unroll
    for (int jj = 0; jj < 16; jj++) { A1[jj] = 0.f; A2[jj] = 0.f; }

    for (int ss = 0; ss < steps; ss++) {
        const int cur = ss & 1;
        __syncthreads();   // buf[cur] staged; prev epilogue done with Rbuf

        if (act) {
            // ---- K=18 GEMM (6x6 fragment) from buf[cur] -> R~ tile ----
            float acc[6][6];
#pragma unroll
            for (int m = 0; m < 6; m++)
#pragma unroll
                for (int n = 0; n < 6; n++) acc[m][n] = 0.f;
            const float* Ap = Abuf[cur] + 6 * ti;
            const float* Bp = Bbuf[cur] + 6 * tj;
#pragma unroll 6
            for (int k = 0; k < 18; k++) {
                float2 a01 = *(const float2*)(Ap + k * ABST);
                float2 a23 = *(const float2*)(Ap + k * ABST + 2);
                float2 a45 = *(const float2*)(Ap + k * ABST + 4);
                float2 b01 = *(const float2*)(Bp + k * ABST);
                float2 b23 = *(const float2*)(Bp + k * ABST + 2);
                float2 b45 = *(const float2*)(Bp + k * ABST + 4);
                float av[6] = {a01.x, a01.y, a23.x, a23.y, a45.x, a45.y};
                float bv[6] = {b01.x, b01.y, b23.x, b23.y, b45.x, b45.y};
#pragma unroll
                for (int m = 0; m < 6; m++)
#pragma unroll
                    for (int n = 0; n < 6; n++)
                        acc[m][n] = fmaf(av[m], bv[n], acc[m][n]);
            }
#pragma unroll
            for (int m = 0; m < 6; m++)
#pragma unroll
                for (int n = 0; n < 6; n++)
                    Rbuf[(6 * ti + m) * RST + 6 * tj + n] = acc[m][n];
        } else if (stager) {
            // ---- stage next row pair into buf[cur^1]; prefetch next-next ----
            if (ss + 1 < steps) {
#pragma unroll
                for (int q = 0; q < 9; q++) if (ok[q]) {
                    Abuf[cur ^ 1][dstA[q]] = rA[q];
                    Bbuf[cur ^ 1][dstA[q] + (m16[q] ? ABST : 0)] = rB[q];
                }
            }
            if (ss + 2 < steps) {
                int pn = lo + ss + 2;
                int ra = CY(pn - 1) * W, rb = CY(pn + d - 1) * W;
#pragma unroll
                for (int q = 0; q < 9; q++) if (ok[q]) {
                    const float* bA = m16[q] ? eSb : s2B;
                    const float* bB = m16[q] ? eTb : tB;
                    rA[q] = __ldg(bA + srcOff[q] + ra);
                    rB[q] = __ldg(bB + srcOff[q] + rb);
                }
            }
        }
        __syncthreads();   // Rbuf writes visible

        // ---- epilogue: diag-x-stencil, sliding window, argmin on finish ----
        const bool fin = (ss >= 2);
        float bd = 3.4e38f;
        int bjj = 0;
#pragma unroll
        for (int jj = 0; jj < 16; jj++) {
            float g = R0[jj] + R1[jj] + R2[jj];
            if (fin) {
                float d2 = A2[jj] + g;
                if (d2 < bd) { bd = d2; bjj = jj; }
            }
            A2[jj] = A1[jj] + g;
            A1[jj] = g;
        }
        if (fin) {
            int iy = lo + ss - 2;
            unsigned jrow = (unsigned)((iy + d) * W + ejx0);
            unsigned long long key =
                ((unsigned long long)__float_as_uint(bd) << 12) | (jrow + bjj);
            atomicMin(gb + iy * W, key);
        }
    }
}

// ---------------------------------------------------------------------------
// Decode packed keys -> (jy, jx, d2).
// ---------------------------------------------------------------------------
__global__ void reduce_kernel(float* __restrict__ out) {
    int idx = blockIdx.x * blockDim.x + threadIdx.x;
    if (idx >= NB * HW) return;
    int b = idx >> 12, q = idx & (HW - 1);
    unsigned long long best = g_best[idx];
    int j = (int)(best & 4095u);
    float d2 = __uint_as_float((unsigned)(best >> 12));
    out[(size_t)b * 2 * HW + q]                    = (float)(j >> 6);
    out[(size_t)b * 2 * HW + HW + q]               = (float)(j & 63);
    out[(size_t)NB * 2 * HW + (size_t)b * HW + q]  = d2;
}

extern "C" void kernel_launch(void* const* d_in, const int* in_sizes, int n_in,
                              void* d_out, int out_size) {
    const float* s = (const float*)d_in[0];
    const float* t = (const float*)d_in[1];
    float* out = (float*)d_out;

    norm1_kernel<<<dim3((NB * HW + 255) / 256, 2), 256>>>(s, t);
    nn_kernel<<<NDIAG * NB, 256>>>(t);
    reduce_kernel<<<(NB * HW + 255) / 256, 256>>>(out);
}